// round 14
// baseline (speedup 1.0000x reference)
#include <cuda_runtime.h>
#include <cuda_bf16.h>
#include <cstdint>

// Problem constants
static constexpr int kS    = 256;
static constexpr int kB    = 16;
static constexpr int kV    = 32000;
static constexpr int kEMB  = 32;
static constexpr int kHID  = 16;
static constexpr int kG    = 4 * kHID;     // 64 gates
static constexpr int kRows = kS * kB;      // 4096
static constexpr int kMT   = 128;          // rows per m tile
static constexpr int kNT   = 128;          // cols per CTA (n tile)
static constexpr int kNTiles = kV / kNT;   // 250
static constexpr int kMTiles = kRows / kMT; // 32
static constexpr int kMLoop = 4;           // m tiles per CTA
static constexpr int kYBlk  = kMTiles / kMLoop;  // 8
static constexpr int kFS   = 24;           // u32 row stride (conflict-free LDS)
static constexpr int kTileU32 = kMT * kFS; // 3072 u32 = 12KB per tile

static constexpr float kLOG2E = 1.4426950408889634f;

// dynamic smem: A[4] tiles + B tile + bias + lz
static constexpr int kSmemBytes =
    (4 * kTileU32 + kTileU32) * 4 + kNT * 4 + kMLoop * kMT * 4;  // 64 KB

// Scratch (static __device__ — no allocations allowed)
__device__ float    g_gx[kS * kB * kG];
__device__ float    g_concat[kRows * 2 * kHID];   // A matrix [4096][32] f32
__device__ uint32_t g_abf1[kRows * kFS];          // A bf16-frag, x log2(e)
__device__ uint32_t g_abf2[kRows * kFS];          // A bf16-frag, plain
__device__ uint32_t g_bbf[kV * kFS];              // W_out bf16-frag, col-permuted
__device__ float    g_part[kNTiles * kRows];      // per-(ntile,row) exp-sums
__device__ float    g_lz[kRows];                  // per-row logZ

__device__ __forceinline__ float sigf(float x) {
    return 1.0f / (1.0f + __expf(-x));
}
__device__ __forceinline__ float tanhfast(float x) {
    return 2.0f / (1.0f + __expf(-2.0f * x)) - 1.0f;
}
__device__ __forceinline__ float ex2f(float x) {
    float y;
    asm("ex2.approx.ftz.f32 %0, %1;" : "=f"(y) : "f"(x));
    return y;
}
__device__ __forceinline__ uint32_t pack_bf16(float lo, float hi) {
    __nv_bfloat162 h = __floats2bfloat162_rn(lo, hi);
    return *reinterpret_cast<uint32_t*>(&h);
}
__device__ __forceinline__ void mma_bf16(float c[4], uint32_t a0, uint32_t a1,
                                         uint32_t a2, uint32_t a3,
                                         uint32_t b0, uint32_t b1) {
    asm("mma.sync.aligned.m16n8k16.row.col.f32.bf16.bf16.f32 "
        "{%0,%1,%2,%3}, {%4,%5,%6,%7}, {%8,%9}, {%0,%1,%2,%3};"
        : "+f"(c[0]), "+f"(c[1]), "+f"(c[2]), "+f"(c[3])
        : "r"(a0), "r"(a1), "r"(a2), "r"(a3), "r"(b0), "r"(b1));
}
__device__ __forceinline__ void cp16(uint32_t sdst, const void* gsrc) {
    asm volatile("cp.async.cg.shared.global [%0], [%1], 16;"
                 :: "r"(sdst), "l"(gsrc));
}
#define CP_COMMIT() asm volatile("cp.async.commit_group;")
#define CP_WAIT(N)  asm volatile("cp.async.wait_group %0;" :: "n"(N))

// fragment column for k-pair p (p = k/2, 0..15)
__device__ __forceinline__ int fragcol(int p) {
    return 2 * (p & 3) + ((p >> 2) & 1) + (p >> 3) * 8;
}
// Column permutation within a 128-col tile (pass-2 STG.128 enabling):
//   l = 16q + 4tg + e  ->  frag = 2q + (e>>1), pos_in_frag = tg*2 + (e&1)
__device__ __forceinline__ int permrow(int l) {
    int q = l >> 4, tgp = (l >> 2) & 3, e = l & 3;
    return (2 * q + (e >> 1)) * 8 + tgp * 2 + (e & 1);
}

// ---------------------------------------------------------------------------
// Kernel 0: Gx = x@W_ih.T + b_ih + b_hh. 256 blocks x 16 positions each:
// W_ih staged ONCE per block, reused over 4 m-iterations of 4 positions.
// ---------------------------------------------------------------------------
__global__ void gx_kernel(const int* __restrict__ tokens,
                          const float* __restrict__ emb,
                          const float* __restrict__ W_ih,
                          const float* __restrict__ b_ih,
                          const float* __restrict__ b_hh) {
    __shared__ float ws[kG * 33];
    __shared__ float xs[16][32];
    __shared__ float bb[kG];

    int tid = threadIdx.x;
    for (int i = tid; i < kG * kEMB; i += 256)
        ws[(i >> 5) * 33 + (i & 31)] = W_ih[i];
    if (tid < kG) bb[tid] = b_ih[tid] + b_hh[tid];

    int sb0 = blockIdx.x * 16;
    for (int i = tid; i < 16 * 32; i += 256) {
        int g = i >> 5, k = i & 31;
        xs[g][k] = emb[(size_t)tokens[sb0 + g] * kEMB + k];
    }
    __syncthreads();

    int j = tid & (kG - 1);
    const float* wr = ws + j * 33;
    float bj = bb[j];
#pragma unroll
    for (int mi = 0; mi < 4; ++mi) {
        int g = mi * 4 + (tid >> 6);
        float a0 = bj, a1 = 0.f, a2 = 0.f, a3 = 0.f;
#pragma unroll
        for (int k = 0; k < kEMB; k += 4) {
            a0 += xs[g][k + 0] * wr[k + 0];
            a1 += xs[g][k + 1] * wr[k + 1];
            a2 += xs[g][k + 2] * wr[k + 2];
            a3 += xs[g][k + 3] * wr[k + 3];
        }
        g_gx[(sb0 + g) * kG + j] = (a0 + a1) + (a2 + a3);
    }
}

// ---------------------------------------------------------------------------
// Kernel 1: warp-synchronous LSTM. 32 blocks = (2 dirs) x (16 batch lanes),
// 32 threads each; thread t owns gates t and t+32. h broadcast via shfl —
// ZERO barriers, zero smem. Gate order (i,f,g,o): act_lo = sig(i|f),
// act_hi = tanh(g) for t<16, sig(o) for t>=16.
// ---------------------------------------------------------------------------
__global__ void lstm_kernel(const float* __restrict__ W_hh,
                            const float* __restrict__ init_h,
                            const float* __restrict__ init_c) {
    int dir  = blockIdx.x >> 4;
    int b    = blockIdx.x & 15;
    int lane = threadIdx.x;               // 0..31

    float wlo[kHID], whi[kHID];
#pragma unroll
    for (int k = 0; k < kHID; ++k) {
        wlo[k] = W_hh[lane * kHID + k];
        whi[k] = W_hh[(lane + 32) * kHID + k];
    }

    float c_reg = 0.f, h_reg = 0.f;
    if (lane < kHID) {
        h_reg = init_h[lane];
        c_reg = init_c[lane];
    }

    int p  = dir ? (kS - 1) : 0;
    int dp = dir ? -1 : 1;
    float gxlo = g_gx[(p * kB + b) * kG + lane];
    float gxhi = g_gx[(p * kB + b) * kG + lane + 32];

    for (int step = 0; step < kS; ++step, p += dp) {
        float glo = gxlo, ghi = gxhi;
        if (step < kS - 1) {
            int pn = p + dp;
            gxlo = g_gx[(pn * kB + b) * kG + lane];
            gxhi = g_gx[(pn * kB + b) * kG + lane + 32];
        }

        // emit hidden used for prediction at position p (pre-consume)
        if (lane < kHID)
            g_concat[(p * kB + b) * (2 * kHID) + dir * kHID + lane] = h_reg;

        // gate pre-activations: dot(h, W_hh row) via shfl broadcast
        float a0 = glo, a1 = 0.f, b0 = ghi, b1 = 0.f;
#pragma unroll
        for (int k = 0; k < kHID; k += 2) {
            float hk0 = __shfl_sync(0xffffffffu, h_reg, k);
            float hk1 = __shfl_sync(0xffffffffu, h_reg, k + 1);
            a0 += wlo[k] * hk0;     b0 += whi[k] * hk0;
            a1 += wlo[k + 1] * hk1; b1 += whi[k + 1] * hk1;
        }
        float pre_lo = a0 + a1;               // gates 0..31: i (t<16), f
        float pre_hi = b0 + b1;               // gates 32..63: g (t<16), o
        float act_lo = sigf(pre_lo);
        float act_hi = (lane < kHID) ? tanhfast(pre_hi) : sigf(pre_hi);

        float fj = __shfl_sync(0xffffffffu, act_lo, (lane & 15) + 16);
        float oj = __shfl_sync(0xffffffffu, act_hi, (lane & 15) + 16);

        if (lane < kHID) {
            c_reg = fj * c_reg + act_lo * act_hi;   // sig(f)c + sig(i)tanh(g)
            h_reg = oj * tanhfast(c_reg);
        }
    }
}

// ---------------------------------------------------------------------------
// Prep kernels. prepb applies the within-tile column permutation (permrow).
// ---------------------------------------------------------------------------
__global__ void prepb_kernel(const float* __restrict__ W_out) {
    int i = blockIdx.x * 256 + threadIdx.x;       // over kV*8 float4s
    float4 v = reinterpret_cast<const float4*>(W_out)[i];
    int n = i >> 3, j = i & 7;
    int rp = (n & ~127) + permrow(n & 127);       // permuted physical row
    uint32_t* dst = g_bbf + (size_t)rp * kFS;
    dst[fragcol(2 * j)]     = pack_bf16(v.x, v.y);
    dst[fragcol(2 * j + 1)] = pack_bf16(v.z, v.w);
}

__global__ void prepa_kernel() {
    int i = blockIdx.x * 256 + threadIdx.x;       // over kRows*8 float4s
    float4 v = reinterpret_cast<const float4*>(g_concat)[i];
    int r = i >> 3, j = i & 7;
    int c0 = fragcol(2 * j), c1 = fragcol(2 * j + 1);
    g_abf2[r * kFS + c0] = pack_bf16(v.x, v.y);
    g_abf2[r * kFS + c1] = pack_bf16(v.z, v.w);
    g_abf1[r * kFS + c0] = pack_bf16(v.x * kLOG2E, v.y * kLOG2E);
    g_abf1[r * kFS + c1] = pack_bf16(v.z * kLOG2E, v.w * kLOG2E);
}

// ---------------------------------------------------------------------------
// Kernel 2: bf16 tensor-core logits GEMM. Grid (250, 8). cp.async prefetch of
// B + 4 A tiles at CTA start; m-loop is wait/barrier/MMA only.
// Pass 1 (WRITE=false): Σ ex2 -> g_part. Pass 2: acc init = b - logZ ->
// STG.128 direct fragment stores (column-permuted B).
// ---------------------------------------------------------------------------
template <bool WRITE>
__global__ void __launch_bounds__(256, 2)
mma_pass(const float* __restrict__ b_out, float* __restrict__ out) {
    extern __shared__ uint32_t dynsm[];
    uint32_t* A_sm   = dynsm;                       // [4][3072]
    uint32_t* B_sm   = dynsm + 4 * kTileU32;        // [3072]
    float*    bias_sm = reinterpret_cast<float*>(dynsm + 5 * kTileU32);  // [128]
    float*    lz_sm   = bias_sm + kNT;              // [512]

    int tid  = threadIdx.x;
    int warp = tid >> 5;
    int lane = tid & 31;
    int tg   = lane & 3;
    int gr   = lane >> 2;
    int n0   = blockIdx.x * kNT;
    int mrow = warp * 16;
    int rbase = blockIdx.y * kMLoop * kMT;          // 512 rows per CTA

    // B tile: contiguous 12KB from g_bbf
    {
        uint32_t bdst = (uint32_t)__cvta_generic_to_shared(B_sm);
        const uint4* src = reinterpret_cast<const uint4*>(
            g_bbf + (size_t)n0 * kFS);
        for (int i = tid; i < kTileU32 / 4; i += 256)
            cp16(bdst + i * 16, src + i);
        CP_COMMIT();
    }
    // A tiles: 4 contiguous 12KB blocks
    const uint32_t* asrc_base = WRITE ? g_abf2 : g_abf1;
#pragma unroll
    for (int mi = 0; mi < kMLoop; ++mi) {
        uint32_t adst = (uint32_t)__cvta_generic_to_shared(A_sm + mi * kTileU32);
        const uint4* src = reinterpret_cast<const uint4*>(
            asrc_base + (size_t)(rbase + mi * kMT) * kFS);
        for (int i = tid; i < kTileU32 / 4; i += 256)
            cp16(adst + i * 16, src + i);
        CP_COMMIT();
    }
    // bias (PHYSICAL fragment order, matching permuted B) + lz
    if (tid < kNT) {
        int frag = tid >> 3, pos = tid & 7;
        int l = 16 * (frag >> 1) + 4 * (pos >> 1) + 2 * (frag & 1) + (pos & 1);
        float bv = b_out[n0 + l];
        bias_sm[tid] = WRITE ? bv : bv * kLOG2E;
    }
    if (WRITE) {
        for (int i = tid; i < kMLoop * kMT; i += 256)
            lz_sm[i] = g_lz[rbase + i];
    }

#pragma unroll
    for (int mi = 0; mi < kMLoop; ++mi) {
        switch (mi) {   // wait until B + A[0..mi] groups complete
            case 0:  CP_WAIT(3); break;
            case 1:  CP_WAIT(2); break;
            case 2:  CP_WAIT(1); break;
            default: CP_WAIT(0); break;
        }
        __syncthreads();

        int row0 = rbase + mi * kMT;
        const uint32_t* At = A_sm + mi * kTileU32;

        float c[16][4];
#pragma unroll
        for (int f = 0; f < 16; ++f) {
            float bx = bias_sm[f * 8 + tg * 2];
            float by = bias_sm[f * 8 + tg * 2 + 1];
            if (WRITE) {
                float z0 = lz_sm[mi * kMT + mrow + gr];
                float z1 = lz_sm[mi * kMT + mrow + gr + 8];
                c[f][0] = bx - z0; c[f][1] = by - z0;
                c[f][2] = bx - z1; c[f][3] = by - z1;
            } else {
                c[f][0] = bx; c[f][1] = by;
                c[f][2] = bx; c[f][3] = by;
            }
        }

        const uint32_t* ar0 = At + (mrow + gr) * kFS + tg * 2;
        const uint32_t* ar1 = At + (mrow + gr + 8) * kFS + tg * 2;
        uint2 alo0 = *reinterpret_cast<const uint2*>(ar0);
        uint2 alo1 = *reinterpret_cast<const uint2*>(ar1);
        uint2 ahi0 = *reinterpret_cast<const uint2*>(ar0 + 8);
        uint2 ahi1 = *reinterpret_cast<const uint2*>(ar1 + 8);
        const uint32_t* bp = B_sm + gr * kFS + tg * 2;

#pragma unroll
        for (int f = 0; f < 16; ++f) {
            uint2 blo = *reinterpret_cast<const uint2*>(bp + f * 8 * kFS);
            uint2 bhi = *reinterpret_cast<const uint2*>(bp + f * 8 * kFS + 8);
            mma_bf16(c[f], alo0.x, alo1.x, alo0.y, alo1.y, blo.x, blo.y);
            mma_bf16(c[f], ahi0.x, ahi1.x, ahi0.y, ahi1.y, bhi.x, bhi.y);
        }

        if (!WRITE) {
            float s0 = 0.f, s1 = 0.f;
#pragma unroll
            for (int f = 0; f < 16; ++f) {
                s0 += ex2f(c[f][0]) + ex2f(c[f][1]);
                s1 += ex2f(c[f][2]) + ex2f(c[f][3]);
            }
            s0 += __shfl_xor_sync(0xffffffffu, s0, 1);
            s0 += __shfl_xor_sync(0xffffffffu, s0, 2);
            s1 += __shfl_xor_sync(0xffffffffu, s1, 1);
            s1 += __shfl_xor_sync(0xffffffffu, s1, 2);
            if (tg == 0) {
                g_part[(size_t)blockIdx.x * kRows + row0 + mrow + gr]     = s0;
                g_part[(size_t)blockIdx.x * kRows + row0 + mrow + gr + 8] = s1;
            }
        } else {
            // STG.128: frag pair (2q,2q+1) slots = logical cols 16q+4tg..+3
            float* orow0 = out + (size_t)(row0 + mrow + gr) * kV + n0 + tg * 4;
            float* orow1 = orow0 + (size_t)8 * kV;
#pragma unroll
            for (int q = 0; q < 8; ++q) {
                __stcs(reinterpret_cast<float4*>(orow0 + q * 16),
                       make_float4(c[2 * q][0], c[2 * q][1],
                                   c[2 * q + 1][0], c[2 * q + 1][1]));
                __stcs(reinterpret_cast<float4*>(orow1 + q * 16),
                       make_float4(c[2 * q][2], c[2 * q][3],
                                   c[2 * q + 1][2], c[2 * q + 1][3]));
            }
        }
    }
}

// ---------------------------------------------------------------------------
// Kernel 3: logZ reduce. 256 blocks x 128 threads = 16 rows x 8 t-slices.
// ---------------------------------------------------------------------------
__global__ void logz_kernel() {
    __shared__ float red[8][16];
    int rl    = threadIdx.x & 15;
    int slice = threadIdx.x >> 4;
    int row   = blockIdx.x * 16 + rl;

    float s = 0.f;
#pragma unroll 4
    for (int t = slice; t < kNTiles; t += 8)
        s += g_part[(size_t)t * kRows + row];
    red[slice][rl] = s;
    __syncthreads();

    if (threadIdx.x < 16) {
        float tot = 0.f;
#pragma unroll
        for (int i = 0; i < 8; ++i) tot += red[i][rl];
        g_lz[row] = __logf(tot);
    }
}

// ---------------------------------------------------------------------------
extern "C" void kernel_launch(void* const* d_in, const int* in_sizes, int n_in,
                              void* d_out, int out_size) {
    const int*   tokens = (const int*)d_in[0];
    const float* emb    = (const float*)d_in[1];
    const float* W_ih   = (const float*)d_in[2];
    const float* W_hh   = (const float*)d_in[3];
    const float* b_ih   = (const float*)d_in[4];
    const float* b_hh   = (const float*)d_in[5];
    const float* W_out  = (const float*)d_in[6];
    const float* b_out  = (const float*)d_in[7];
    const float* init_h = (const float*)d_in[8];
    const float* init_c = (const float*)d_in[9];
    float* out = (float*)d_out;

    static cudaStream_t s1 = nullptr;
    static cudaEvent_t evFork = nullptr, evB = nullptr;
    static bool attr_set = false;
    if (!attr_set) {
        cudaFuncSetAttribute(mma_pass<false>,
                             cudaFuncAttributeMaxDynamicSharedMemorySize,
                             kSmemBytes);
        cudaFuncSetAttribute(mma_pass<true>,
                             cudaFuncAttributeMaxDynamicSharedMemorySize,
                             kSmemBytes);
        cudaStreamCreateWithFlags(&s1, cudaStreamNonBlocking);
        cudaEventCreateWithFlags(&evFork, cudaEventDisableTiming);
        cudaEventCreateWithFlags(&evB, cudaEventDisableTiming);
        attr_set = true;
    }

    dim3 grid(kNTiles, kYBlk);

    // fork: prepb (depends only on W_out) overlaps gx+lstm+prepa
    cudaEventRecord(evFork, 0);
    cudaStreamWaitEvent(s1, evFork, 0);
    prepb_kernel<<<kV * 8 / 256, 256, 0, s1>>>(W_out);
    cudaEventRecord(evB, s1);

    gx_kernel<<<kRows / 16, 256>>>(tokens, emb, W_ih, b_ih, b_hh);
    lstm_kernel<<<32, 32>>>(W_hh, init_h, init_c);
    prepa_kernel<<<kRows * 8 / 256, 256>>>();
    cudaStreamWaitEvent(0, evB, 0);

    mma_pass<false><<<grid, 256, kSmemBytes>>>(b_out, out);
    logz_kernel<<<kRows / 16, 128>>>();
    mma_pass<true><<<grid, 256, kSmemBytes>>>(b_out, out);
}

// round 15
// speedup vs baseline: 1.0165x; 1.0165x over previous
#include <cuda_runtime.h>
#include <cuda_bf16.h>
#include <cuda_fp16.h>
#include <cstdint>

// Problem constants
static constexpr int kS    = 256;
static constexpr int kB    = 16;
static constexpr int kV    = 32000;
static constexpr int kEMB  = 32;
static constexpr int kHID  = 16;
static constexpr int kG    = 4 * kHID;     // 64 gates
static constexpr int kRows = kS * kB;      // 4096
static constexpr int kMT   = 128;          // rows per m tile
static constexpr int kNT   = 128;          // cols per CTA (n tile)
static constexpr int kNTiles = kV / kNT;   // 250
static constexpr int kMTiles = kRows / kMT; // 32
static constexpr int kMLoop = 4;           // m tiles per CTA
static constexpr int kYBlk  = kMTiles / kMLoop;  // 8
static constexpr int kFS   = 24;           // u32 row stride (conflict-free LDS)
static constexpr int kTileU32 = kMT * kFS; // 3072 u32 = 12KB per tile

static constexpr float kLOG2E = 1.4426950408889634f;

// dynamic smem: A[4] tiles + B tile + bias + lz
static constexpr int kSmemBytes =
    (4 * kTileU32 + kTileU32) * 4 + kNT * 4 + kMLoop * kMT * 4;  // 64 KB

// Scratch (static __device__ — no allocations allowed)
__device__ float    g_gx[kS * kB * kG];
__device__ float    g_concat[kRows * 2 * kHID];   // A matrix [4096][32] f32
__device__ uint32_t g_abf1[kRows * kFS];          // A bf16-frag, x log2(e)
__device__ uint32_t g_abf2[kRows * kFS];          // A bf16-frag, plain
__device__ uint32_t g_bbf[kV * kFS];              // W_out bf16-frag, col-permuted
__device__ float    g_part[kNTiles * kRows];      // per-(ntile,row) exp-sums
__device__ float    g_lz[kRows];                  // per-row logZ

__device__ __forceinline__ float sigf(float x) {
    return 1.0f / (1.0f + __expf(-x));
}
__device__ __forceinline__ float tanhfast(float x) {
    return 2.0f / (1.0f + __expf(-2.0f * x)) - 1.0f;
}
__device__ __forceinline__ uint32_t pack_bf16(float lo, float hi) {
    __nv_bfloat162 h = __floats2bfloat162_rn(lo, hi);
    return *reinterpret_cast<uint32_t*>(&h);
}
__device__ __forceinline__ void mma_bf16(float c[4], uint32_t a0, uint32_t a1,
                                         uint32_t a2, uint32_t a3,
                                         uint32_t b0, uint32_t b1) {
    asm("mma.sync.aligned.m16n8k16.row.col.f32.bf16.bf16.f32 "
        "{%0,%1,%2,%3}, {%4,%5,%6,%7}, {%8,%9}, {%0,%1,%2,%3};"
        : "+f"(c[0]), "+f"(c[1]), "+f"(c[2]), "+f"(c[3])
        : "r"(a0), "r"(a1), "r"(a2), "r"(a3), "r"(b0), "r"(b1));
}
__device__ __forceinline__ void cp16(uint32_t sdst, const void* gsrc) {
    asm volatile("cp.async.cg.shared.global [%0], [%1], 16;"
                 :: "r"(sdst), "l"(gsrc));
}
#define CP_COMMIT() asm volatile("cp.async.commit_group;")
#define CP_WAIT(N)  asm volatile("cp.async.wait_group %0;" :: "n"(N))

// fragment column for k-pair p (p = k/2, 0..15)
__device__ __forceinline__ int fragcol(int p) {
    return 2 * (p & 3) + ((p >> 2) & 1) + (p >> 3) * 8;
}
// Column permutation within a 128-col tile (pass-2 STG.128 enabling):
//   l = 16q + 4tg + e  ->  frag = 2q + (e>>1), pos_in_frag = tg*2 + (e&1)
__device__ __forceinline__ int permrow(int l) {
    int q = l >> 4, tgp = (l >> 2) & 3, e = l & 3;
    return (2 * q + (e >> 1)) * 8 + tgp * 2 + (e & 1);
}

// ---------------------------------------------------------------------------
// Kernel 0: Gx = x@W_ih.T + b_ih + b_hh. 256 blocks x 16 positions each:
// W_ih staged ONCE per block, reused over 4 m-iterations of 4 positions.
// ---------------------------------------------------------------------------
__global__ void gx_kernel(const int* __restrict__ tokens,
                          const float* __restrict__ emb,
                          const float* __restrict__ W_ih,
                          const float* __restrict__ b_ih,
                          const float* __restrict__ b_hh) {
    __shared__ float ws[kG * 33];
    __shared__ float xs[16][32];
    __shared__ float bb[kG];

    int tid = threadIdx.x;
    for (int i = tid; i < kG * kEMB; i += 256)
        ws[(i >> 5) * 33 + (i & 31)] = W_ih[i];
    if (tid < kG) bb[tid] = b_ih[tid] + b_hh[tid];

    int sb0 = blockIdx.x * 16;
    for (int i = tid; i < 16 * 32; i += 256) {
        int g = i >> 5, k = i & 31;
        xs[g][k] = emb[(size_t)tokens[sb0 + g] * kEMB + k];
    }
    __syncthreads();

    int j = tid & (kG - 1);
    const float* wr = ws + j * 33;
    float bj = bb[j];
#pragma unroll
    for (int mi = 0; mi < 4; ++mi) {
        int g = mi * 4 + (tid >> 6);
        float a0 = bj, a1 = 0.f, a2 = 0.f, a3 = 0.f;
#pragma unroll
        for (int k = 0; k < kEMB; k += 4) {
            a0 += xs[g][k + 0] * wr[k + 0];
            a1 += xs[g][k + 1] * wr[k + 1];
            a2 += xs[g][k + 2] * wr[k + 2];
            a3 += xs[g][k + 3] * wr[k + 3];
        }
        g_gx[(sb0 + g) * kG + j] = (a0 + a1) + (a2 + a3);
    }
}

// ---------------------------------------------------------------------------
// Kernel 1: LSTM recurrence (proven R13 version). 32 blocks =
// (2 dirs) x (16 batch lanes), 64 threads = one per gate, 2 barriers/step.
// ---------------------------------------------------------------------------
__global__ void lstm_kernel(const float* __restrict__ W_hh,
                            const float* __restrict__ init_h,
                            const float* __restrict__ init_c) {
    int dir = blockIdx.x >> 4;
    int b   = blockIdx.x & 15;
    int j   = threadIdx.x;

    __shared__ float h_sh[kHID];
    __shared__ float gact[kG];

    float w[kHID];
#pragma unroll
    for (int k = 0; k < kHID; ++k) w[k] = W_hh[j * kHID + k];

    float c_reg = 0.f, h_reg = 0.f;
    if (j < kHID) {
        h_reg = init_h[j];
        c_reg = init_c[j];
        h_sh[j] = h_reg;
    }
    __syncthreads();

    int p  = dir ? (kS - 1) : 0;
    int dp = dir ? -1 : 1;
    float gx_next = g_gx[(p * kB + b) * kG + j];

    for (int step = 0; step < kS; ++step, p += dp) {
        float gxv = gx_next;
        if (step < kS - 1) gx_next = g_gx[((p + dp) * kB + b) * kG + j];

        if (j < kHID)
            g_concat[(p * kB + b) * (2 * kHID) + dir * kHID + j] = h_reg;

        float a0 = 0.f, a1 = 0.f, a2 = 0.f, a3 = 0.f;
#pragma unroll
        for (int k = 0; k < kHID; k += 4) {
            a0 += w[k + 0] * h_sh[k + 0];
            a1 += w[k + 1] * h_sh[k + 1];
            a2 += w[k + 2] * h_sh[k + 2];
            a3 += w[k + 3] * h_sh[k + 3];
        }
        float pre = gxv + ((a0 + a1) + (a2 + a3));
        gact[j] = (j >= 32 && j < 48) ? tanhfast(pre) : sigf(pre);
        __syncthreads();

        if (j < kHID) {
            float ig = gact[j];
            float fg = gact[kHID + j];
            float gg = gact[2 * kHID + j];
            float og = gact[3 * kHID + j];
            c_reg = fg * c_reg + ig * gg;
            h_reg = og * tanhfast(c_reg);
            h_sh[j] = h_reg;
        }
        __syncthreads();
    }
}

// ---------------------------------------------------------------------------
// Prep kernels. prepb applies the within-tile column permutation (permrow).
// ---------------------------------------------------------------------------
__global__ void prepb_kernel(const float* __restrict__ W_out) {
    int i = blockIdx.x * 256 + threadIdx.x;       // over kV*8 float4s
    float4 v = reinterpret_cast<const float4*>(W_out)[i];
    int n = i >> 3, j = i & 7;
    int rp = (n & ~127) + permrow(n & 127);       // permuted physical row
    uint32_t* dst = g_bbf + (size_t)rp * kFS;
    dst[fragcol(2 * j)]     = pack_bf16(v.x, v.y);
    dst[fragcol(2 * j + 1)] = pack_bf16(v.z, v.w);
}

__global__ void prepa_kernel() {
    int i = blockIdx.x * 256 + threadIdx.x;       // over kRows*8 float4s
    float4 v = reinterpret_cast<const float4*>(g_concat)[i];
    int r = i >> 3, j = i & 7;
    int c0 = fragcol(2 * j), c1 = fragcol(2 * j + 1);
    g_abf2[r * kFS + c0] = pack_bf16(v.x, v.y);
    g_abf2[r * kFS + c1] = pack_bf16(v.z, v.w);
    g_abf1[r * kFS + c0] = pack_bf16(v.x * kLOG2E, v.y * kLOG2E);
    g_abf1[r * kFS + c1] = pack_bf16(v.z * kLOG2E, v.w * kLOG2E);
}

// ---------------------------------------------------------------------------
// Kernel 2: bf16 tensor-core logits GEMM. Grid (250, 8). cp.async prefetch of
// B + 4 A tiles at CTA start; m-loop is wait/barrier/MMA only.
// Pass 1 (WRITE=false): Σ 2^x via ex2.approx.f16x2 (h2exp2) — halves MUFU
//   instruction count vs f32 ex2; fp16 chain bounded < 65504 by |logit|<=8.3.
// Pass 2 (WRITE=true): acc init = b - logZ -> STG.128 direct fragment stores.
// ---------------------------------------------------------------------------
template <bool WRITE>
__global__ void __launch_bounds__(256, 2)
mma_pass(const float* __restrict__ b_out, float* __restrict__ out) {
    extern __shared__ uint32_t dynsm[];
    uint32_t* A_sm   = dynsm;                       // [4][3072]
    uint32_t* B_sm   = dynsm + 4 * kTileU32;        // [3072]
    float*    bias_sm = reinterpret_cast<float*>(dynsm + 5 * kTileU32);  // [128]
    float*    lz_sm   = bias_sm + kNT;              // [512]

    int tid  = threadIdx.x;
    int warp = tid >> 5;
    int lane = tid & 31;
    int tg   = lane & 3;
    int gr   = lane >> 2;
    int n0   = blockIdx.x * kNT;
    int mrow = warp * 16;
    int rbase = blockIdx.y * kMLoop * kMT;          // 512 rows per CTA

    // B tile: contiguous 12KB from g_bbf
    {
        uint32_t bdst = (uint32_t)__cvta_generic_to_shared(B_sm);
        const uint4* src = reinterpret_cast<const uint4*>(
            g_bbf + (size_t)n0 * kFS);
        for (int i = tid; i < kTileU32 / 4; i += 256)
            cp16(bdst + i * 16, src + i);
        CP_COMMIT();
    }
    // A tiles: 4 contiguous 12KB blocks
    const uint32_t* asrc_base = WRITE ? g_abf2 : g_abf1;
#pragma unroll
    for (int mi = 0; mi < kMLoop; ++mi) {
        uint32_t adst = (uint32_t)__cvta_generic_to_shared(A_sm + mi * kTileU32);
        const uint4* src = reinterpret_cast<const uint4*>(
            asrc_base + (size_t)(rbase + mi * kMT) * kFS);
        for (int i = tid; i < kTileU32 / 4; i += 256)
            cp16(adst + i * 16, src + i);
        CP_COMMIT();
    }
    // bias (PHYSICAL fragment order, matching permuted B) + lz
    if (tid < kNT) {
        int frag = tid >> 3, pos = tid & 7;
        int l = 16 * (frag >> 1) + 4 * (pos >> 1) + 2 * (frag & 1) + (pos & 1);
        float bv = b_out[n0 + l];
        bias_sm[tid] = WRITE ? bv : bv * kLOG2E;
    }
    if (WRITE) {
        for (int i = tid; i < kMLoop * kMT; i += 256)
            lz_sm[i] = g_lz[rbase + i];
    }

#pragma unroll
    for (int mi = 0; mi < kMLoop; ++mi) {
        switch (mi) {   // wait until B + A[0..mi] groups complete
            case 0:  CP_WAIT(3); break;
            case 1:  CP_WAIT(2); break;
            case 2:  CP_WAIT(1); break;
            default: CP_WAIT(0); break;
        }
        __syncthreads();

        int row0 = rbase + mi * kMT;
        const uint32_t* At = A_sm + mi * kTileU32;

        float c[16][4];
#pragma unroll
        for (int f = 0; f < 16; ++f) {
            float bx = bias_sm[f * 8 + tg * 2];
            float by = bias_sm[f * 8 + tg * 2 + 1];
            if (WRITE) {
                float z0 = lz_sm[mi * kMT + mrow + gr];
                float z1 = lz_sm[mi * kMT + mrow + gr + 8];
                c[f][0] = bx - z0; c[f][1] = by - z0;
                c[f][2] = bx - z1; c[f][3] = by - z1;
            } else {
                c[f][0] = bx; c[f][1] = by;
                c[f][2] = bx; c[f][3] = by;
            }
        }

        const uint32_t* ar0 = At + (mrow + gr) * kFS + tg * 2;
        const uint32_t* ar1 = At + (mrow + gr + 8) * kFS + tg * 2;
        uint2 alo0 = *reinterpret_cast<const uint2*>(ar0);
        uint2 alo1 = *reinterpret_cast<const uint2*>(ar1);
        uint2 ahi0 = *reinterpret_cast<const uint2*>(ar0 + 8);
        uint2 ahi1 = *reinterpret_cast<const uint2*>(ar1 + 8);
        const uint32_t* bp = B_sm + gr * kFS + tg * 2;

#pragma unroll
        for (int f = 0; f < 16; ++f) {
            uint2 blo = *reinterpret_cast<const uint2*>(bp + f * 8 * kFS);
            uint2 bhi = *reinterpret_cast<const uint2*>(bp + f * 8 * kFS + 8);
            mma_bf16(c[f], alo0.x, alo1.x, alo0.y, alo1.y, blo.x, blo.y);
            mma_bf16(c[f], ahi0.x, ahi1.x, ahi0.y, ahi1.y, bhi.x, bhi.y);
        }

        if (!WRITE) {
            // per-row sum(2^x): fp16x2 ex2 (half the MUFU instructions)
            __half2 acc0 = __float2half2_rn(0.f);
            __half2 acc1 = __float2half2_rn(0.f);
#pragma unroll
            for (int f = 0; f < 16; ++f) {
                acc0 = __hadd2(acc0, h2exp2(__floats2half2_rn(c[f][0], c[f][1])));
                acc1 = __hadd2(acc1, h2exp2(__floats2half2_rn(c[f][2], c[f][3])));
            }
            float2 f0 = __half22float2(acc0);
            float2 f1 = __half22float2(acc1);
            float s0 = f0.x + f0.y;
            float s1 = f1.x + f1.y;
            s0 += __shfl_xor_sync(0xffffffffu, s0, 1);
            s0 += __shfl_xor_sync(0xffffffffu, s0, 2);
            s1 += __shfl_xor_sync(0xffffffffu, s1, 1);
            s1 += __shfl_xor_sync(0xffffffffu, s1, 2);
            if (tg == 0) {
                g_part[(size_t)blockIdx.x * kRows + row0 + mrow + gr]     = s0;
                g_part[(size_t)blockIdx.x * kRows + row0 + mrow + gr + 8] = s1;
            }
        } else {
            // STG.128: frag pair (2q,2q+1) slots = logical cols 16q+4tg..+3
            float* orow0 = out + (size_t)(row0 + mrow + gr) * kV + n0 + tg * 4;
            float* orow1 = orow0 + (size_t)8 * kV;
#pragma unroll
            for (int q = 0; q < 8; ++q) {
                __stcs(reinterpret_cast<float4*>(orow0 + q * 16),
                       make_float4(c[2 * q][0], c[2 * q][1],
                                   c[2 * q + 1][0], c[2 * q + 1][1]));
                __stcs(reinterpret_cast<float4*>(orow1 + q * 16),
                       make_float4(c[2 * q][2], c[2 * q][3],
                                   c[2 * q + 1][2], c[2 * q + 1][3]));
            }
        }
    }
}

// ---------------------------------------------------------------------------
// Kernel 3: logZ reduce. 256 blocks x 128 threads = 16 rows x 8 t-slices.
// ---------------------------------------------------------------------------
__global__ void logz_kernel() {
    __shared__ float red[8][16];
    int rl    = threadIdx.x & 15;
    int slice = threadIdx.x >> 4;
    int row   = blockIdx.x * 16 + rl;

    float s = 0.f;
#pragma unroll 4
    for (int t = slice; t < kNTiles; t += 8)
        s += g_part[(size_t)t * kRows + row];
    red[slice][rl] = s;
    __syncthreads();

    if (threadIdx.x < 16) {
        float tot = 0.f;
#pragma unroll
        for (int i = 0; i < 8; ++i) tot += red[i][rl];
        g_lz[row] = __logf(tot);
    }
}

// ---------------------------------------------------------------------------
extern "C" void kernel_launch(void* const* d_in, const int* in_sizes, int n_in,
                              void* d_out, int out_size) {
    const int*   tokens = (const int*)d_in[0];
    const float* emb    = (const float*)d_in[1];
    const float* W_ih   = (const float*)d_in[2];
    const float* W_hh   = (const float*)d_in[3];
    const float* b_ih   = (const float*)d_in[4];
    const float* b_hh   = (const float*)d_in[5];
    const float* W_out  = (const float*)d_in[6];
    const float* b_out  = (const float*)d_in[7];
    const float* init_h = (const float*)d_in[8];
    const float* init_c = (const float*)d_in[9];
    float* out = (float*)d_out;

    static cudaStream_t s1 = nullptr;
    static cudaEvent_t evFork = nullptr, evB = nullptr;
    static bool attr_set = false;
    if (!attr_set) {
        cudaFuncSetAttribute(mma_pass<false>,
                             cudaFuncAttributeMaxDynamicSharedMemorySize,
                             kSmemBytes);
        cudaFuncSetAttribute(mma_pass<true>,
                             cudaFuncAttributeMaxDynamicSharedMemorySize,
                             kSmemBytes);
        cudaStreamCreateWithFlags(&s1, cudaStreamNonBlocking);
        cudaEventCreateWithFlags(&evFork, cudaEventDisableTiming);
        cudaEventCreateWithFlags(&evB, cudaEventDisableTiming);
        attr_set = true;
    }

    dim3 grid(kNTiles, kYBlk);

    // fork: prepb (depends only on W_out) overlaps gx+lstm+prepa
    cudaEventRecord(evFork, 0);
    cudaStreamWaitEvent(s1, evFork, 0);
    prepb_kernel<<<kV * 8 / 256, 256, 0, s1>>>(W_out);
    cudaEventRecord(evB, s1);

    gx_kernel<<<kRows / 16, 256>>>(tokens, emb, W_ih, b_ih, b_hh);
    lstm_kernel<<<32, 64>>>(W_hh, init_h, init_c);
    prepa_kernel<<<kRows * 8 / 256, 256>>>();
    cudaStreamWaitEvent(0, evB, 0);

    mma_pass<false><<<grid, 256, kSmemBytes>>>(b_out, out);
    logz_kernel<<<kRows / 16, 128>>>();
    mma_pass<true><<<grid, 256, kSmemBytes>>>(b_out, out);
}

// round 16
// speedup vs baseline: 1.0440x; 1.0270x over previous
#include <cuda_runtime.h>
#include <cuda_bf16.h>
#include <cstdint>

// Problem constants
static constexpr int kS    = 256;
static constexpr int kB    = 16;
static constexpr int kV    = 32000;
static constexpr int kEMB  = 32;
static constexpr int kHID  = 16;
static constexpr int kG    = 4 * kHID;     // 64 gates
static constexpr int kRows = kS * kB;      // 4096
static constexpr int kMT   = 128;          // rows per m tile
static constexpr int kNT   = 128;          // cols per CTA (n tile)
static constexpr int kNTiles = kV / kNT;   // 250
static constexpr int kMTiles = kRows / kMT; // 32
static constexpr int kMLoop = 4;           // m tiles per CTA
static constexpr int kYBlk  = kMTiles / kMLoop;  // 8
static constexpr int kFS   = 24;           // u32 row stride (conflict-free LDS)
static constexpr int kTileU32 = kMT * kFS; // 3072 u32 = 12KB per tile

static constexpr float kLOG2E = 1.4426950408889634f;

// dynamic smem: A[4] tiles + B tile + bias + lz
static constexpr int kSmemBytes =
    (4 * kTileU32 + kTileU32) * 4 + kNT * 4 + kMLoop * kMT * 4;  // 64 KB

// Scratch (static __device__ — no allocations allowed)
__device__ float    g_gx[kS * kB * kG];
__device__ float    g_concat[kRows * 2 * kHID];   // A matrix [4096][32] f32
__device__ uint32_t g_abf1[kRows * kFS];          // A bf16-frag, x log2(e)
__device__ uint32_t g_abf2[kRows * kFS];          // A bf16-frag, plain
__device__ uint32_t g_bbf[kV * kFS];              // W_out bf16-frag, col-permuted
__device__ float    g_part[kNTiles * kRows];      // per-(ntile,row) exp-sums
__device__ float    g_lz[kRows];                  // per-row logZ

__device__ __forceinline__ float sigf(float x) {
    return 1.0f / (1.0f + __expf(-x));
}
__device__ __forceinline__ float tanhfast(float x) {
    return 2.0f / (1.0f + __expf(-2.0f * x)) - 1.0f;
}
__device__ __forceinline__ float ex2f(float x) {
    float y;
    asm("ex2.approx.ftz.f32 %0, %1;" : "=f"(y) : "f"(x));
    return y;
}
__device__ __forceinline__ uint32_t pack_bf16(float lo, float hi) {
    __nv_bfloat162 h = __floats2bfloat162_rn(lo, hi);
    return *reinterpret_cast<uint32_t*>(&h);
}
__device__ __forceinline__ void mma_bf16(float c[4], uint32_t a0, uint32_t a1,
                                         uint32_t a2, uint32_t a3,
                                         uint32_t b0, uint32_t b1) {
    asm("mma.sync.aligned.m16n8k16.row.col.f32.bf16.bf16.f32 "
        "{%0,%1,%2,%3}, {%4,%5,%6,%7}, {%8,%9}, {%0,%1,%2,%3};"
        : "+f"(c[0]), "+f"(c[1]), "+f"(c[2]), "+f"(c[3])
        : "r"(a0), "r"(a1), "r"(a2), "r"(a3), "r"(b0), "r"(b1));
}
__device__ __forceinline__ void cp16(uint32_t sdst, const void* gsrc) {
    asm volatile("cp.async.cg.shared.global [%0], [%1], 16;"
                 :: "r"(sdst), "l"(gsrc));
}
#define CP_COMMIT() asm volatile("cp.async.commit_group;")
#define CP_WAIT(N)  asm volatile("cp.async.wait_group %0;" :: "n"(N))

// fragment column for k-pair p (p = k/2, 0..15)
__device__ __forceinline__ int fragcol(int p) {
    return 2 * (p & 3) + ((p >> 2) & 1) + (p >> 3) * 8;
}
// Column permutation within a 128-col tile (pass-2 STG.128 enabling):
//   l = 16q + 4tg + e  ->  frag = 2q + (e>>1), pos_in_frag = tg*2 + (e&1)
__device__ __forceinline__ int permrow(int l) {
    int q = l >> 4, tgp = (l >> 2) & 3, e = l & 3;
    return (2 * q + (e >> 1)) * 8 + tgp * 2 + (e & 1);
}

// ---------------------------------------------------------------------------
// Kernel 0: Gx = x@W_ih.T + b_ih + b_hh. 256 blocks x 16 positions each:
// W_ih staged ONCE per block, reused over 4 m-iterations of 4 positions.
// ---------------------------------------------------------------------------
__global__ void gx_kernel(const int* __restrict__ tokens,
                          const float* __restrict__ emb,
                          const float* __restrict__ W_ih,
                          const float* __restrict__ b_ih,
                          const float* __restrict__ b_hh) {
    __shared__ float ws[kG * 33];
    __shared__ float xs[16][32];
    __shared__ float bb[kG];

    int tid = threadIdx.x;
    for (int i = tid; i < kG * kEMB; i += 256)
        ws[(i >> 5) * 33 + (i & 31)] = W_ih[i];
    if (tid < kG) bb[tid] = b_ih[tid] + b_hh[tid];

    int sb0 = blockIdx.x * 16;
    for (int i = tid; i < 16 * 32; i += 256) {
        int g = i >> 5, k = i & 31;
        xs[g][k] = emb[(size_t)tokens[sb0 + g] * kEMB + k];
    }
    __syncthreads();

    int j = tid & (kG - 1);
    const float* wr = ws + j * 33;
    float bj = bb[j];
#pragma unroll
    for (int mi = 0; mi < 4; ++mi) {
        int g = mi * 4 + (tid >> 6);
        float a0 = bj, a1 = 0.f, a2 = 0.f, a3 = 0.f;
#pragma unroll
        for (int k = 0; k < kEMB; k += 4) {
            a0 += xs[g][k + 0] * wr[k + 0];
            a1 += xs[g][k + 1] * wr[k + 1];
            a2 += xs[g][k + 2] * wr[k + 2];
            a3 += xs[g][k + 3] * wr[k + 3];
        }
        g_gx[(sb0 + g) * kG + j] = (a0 + a1) + (a2 + a3);
    }
}

// ---------------------------------------------------------------------------
// Kernel 1: LSTM recurrence (proven config). 32 blocks =
// (2 dirs) x (16 batch lanes), 64 threads = one per gate, 2 barriers/step.
// ---------------------------------------------------------------------------
__global__ void lstm_kernel(const float* __restrict__ W_hh,
                            const float* __restrict__ init_h,
                            const float* __restrict__ init_c) {
    int dir = blockIdx.x >> 4;
    int b   = blockIdx.x & 15;
    int j   = threadIdx.x;

    __shared__ float h_sh[kHID];
    __shared__ float gact[kG];

    float w[kHID];
#pragma unroll
    for (int k = 0; k < kHID; ++k) w[k] = W_hh[j * kHID + k];

    float c_reg = 0.f, h_reg = 0.f;
    if (j < kHID) {
        h_reg = init_h[j];
        c_reg = init_c[j];
        h_sh[j] = h_reg;
    }
    __syncthreads();

    int p  = dir ? (kS - 1) : 0;
    int dp = dir ? -1 : 1;
    float gx_next = g_gx[(p * kB + b) * kG + j];

    for (int step = 0; step < kS; ++step, p += dp) {
        float gxv = gx_next;
        if (step < kS - 1) gx_next = g_gx[((p + dp) * kB + b) * kG + j];

        if (j < kHID)
            g_concat[(p * kB + b) * (2 * kHID) + dir * kHID + j] = h_reg;

        float a0 = 0.f, a1 = 0.f, a2 = 0.f, a3 = 0.f;
#pragma unroll
        for (int k = 0; k < kHID; k += 4) {
            a0 += w[k + 0] * h_sh[k + 0];
            a1 += w[k + 1] * h_sh[k + 1];
            a2 += w[k + 2] * h_sh[k + 2];
            a3 += w[k + 3] * h_sh[k + 3];
        }
        float pre = gxv + ((a0 + a1) + (a2 + a3));
        gact[j] = (j >= 32 && j < 48) ? tanhfast(pre) : sigf(pre);
        __syncthreads();

        if (j < kHID) {
            float ig = gact[j];
            float fg = gact[kHID + j];
            float gg = gact[2 * kHID + j];
            float og = gact[3 * kHID + j];
            c_reg = fg * c_reg + ig * gg;
            h_reg = og * tanhfast(c_reg);
            h_sh[j] = h_reg;
        }
        __syncthreads();
    }
}

// ---------------------------------------------------------------------------
// Prep kernels. prepb applies the within-tile column permutation (permrow).
// ---------------------------------------------------------------------------
__global__ void prepb_kernel(const float* __restrict__ W_out) {
    int i = blockIdx.x * 256 + threadIdx.x;       // over kV*8 float4s
    float4 v = reinterpret_cast<const float4*>(W_out)[i];
    int n = i >> 3, j = i & 7;
    int rp = (n & ~127) + permrow(n & 127);       // permuted physical row
    uint32_t* dst = g_bbf + (size_t)rp * kFS;
    dst[fragcol(2 * j)]     = pack_bf16(v.x, v.y);
    dst[fragcol(2 * j + 1)] = pack_bf16(v.z, v.w);
}

__global__ void prepa_kernel() {
    int i = blockIdx.x * 256 + threadIdx.x;       // over kRows*8 float4s
    float4 v = reinterpret_cast<const float4*>(g_concat)[i];
    int r = i >> 3, j = i & 7;
    int c0 = fragcol(2 * j), c1 = fragcol(2 * j + 1);
    g_abf2[r * kFS + c0] = pack_bf16(v.x, v.y);
    g_abf2[r * kFS + c1] = pack_bf16(v.z, v.w);
    g_abf1[r * kFS + c0] = pack_bf16(v.x * kLOG2E, v.y * kLOG2E);
    g_abf1[r * kFS + c1] = pack_bf16(v.z * kLOG2E, v.w * kLOG2E);
}

// ---------------------------------------------------------------------------
// Kernel 2: bf16 tensor-core logits GEMM. Grid (250, 8). cp.async prefetch of
// B + 4 A tiles at CTA start; m-loop is wait/barrier/MMA only.
// Pass 1 (WRITE=false): occ 3, Σ f32-ex2 -> g_part.
// Pass 2 (WRITE=true):  occ 2, acc init = b - logZ -> STG.128 direct stores.
// ---------------------------------------------------------------------------
template <bool WRITE>
__global__ void __launch_bounds__(256, WRITE ? 2 : 3)
mma_pass(const float* __restrict__ b_out, float* __restrict__ out) {
    extern __shared__ uint32_t dynsm[];
    uint32_t* A_sm   = dynsm;                       // [4][3072]
    uint32_t* B_sm   = dynsm + 4 * kTileU32;        // [3072]
    float*    bias_sm = reinterpret_cast<float*>(dynsm + 5 * kTileU32);  // [128]
    float*    lz_sm   = bias_sm + kNT;              // [512]

    int tid  = threadIdx.x;
    int warp = tid >> 5;
    int lane = tid & 31;
    int tg   = lane & 3;
    int gr   = lane >> 2;
    int n0   = blockIdx.x * kNT;
    int mrow = warp * 16;
    int rbase = blockIdx.y * kMLoop * kMT;          // 512 rows per CTA

    // B tile: contiguous 12KB from g_bbf
    {
        uint32_t bdst = (uint32_t)__cvta_generic_to_shared(B_sm);
        const uint4* src = reinterpret_cast<const uint4*>(
            g_bbf + (size_t)n0 * kFS);
        for (int i = tid; i < kTileU32 / 4; i += 256)
            cp16(bdst + i * 16, src + i);
        CP_COMMIT();
    }
    // A tiles: 4 contiguous 12KB blocks
    const uint32_t* asrc_base = WRITE ? g_abf2 : g_abf1;
#pragma unroll
    for (int mi = 0; mi < kMLoop; ++mi) {
        uint32_t adst = (uint32_t)__cvta_generic_to_shared(A_sm + mi * kTileU32);
        const uint4* src = reinterpret_cast<const uint4*>(
            asrc_base + (size_t)(rbase + mi * kMT) * kFS);
        for (int i = tid; i < kTileU32 / 4; i += 256)
            cp16(adst + i * 16, src + i);
        CP_COMMIT();
    }
    // bias (PHYSICAL fragment order, matching permuted B) + lz
    if (tid < kNT) {
        int frag = tid >> 3, pos = tid & 7;
        int l = 16 * (frag >> 1) + 4 * (pos >> 1) + 2 * (frag & 1) + (pos & 1);
        float bv = b_out[n0 + l];
        bias_sm[tid] = WRITE ? bv : bv * kLOG2E;
    }
    if (WRITE) {
        for (int i = tid; i < kMLoop * kMT; i += 256)
            lz_sm[i] = g_lz[rbase + i];
    }

#pragma unroll
    for (int mi = 0; mi < kMLoop; ++mi) {
        switch (mi) {   // wait until B + A[0..mi] groups complete
            case 0:  CP_WAIT(3); break;
            case 1:  CP_WAIT(2); break;
            case 2:  CP_WAIT(1); break;
            default: CP_WAIT(0); break;
        }
        __syncthreads();

        int row0 = rbase + mi * kMT;
        const uint32_t* At = A_sm + mi * kTileU32;

        float c[16][4];
#pragma unroll
        for (int f = 0; f < 16; ++f) {
            float bx = bias_sm[f * 8 + tg * 2];
            float by = bias_sm[f * 8 + tg * 2 + 1];
            if (WRITE) {
                float z0 = lz_sm[mi * kMT + mrow + gr];
                float z1 = lz_sm[mi * kMT + mrow + gr + 8];
                c[f][0] = bx - z0; c[f][1] = by - z0;
                c[f][2] = bx - z1; c[f][3] = by - z1;
            } else {
                c[f][0] = bx; c[f][1] = by;
                c[f][2] = bx; c[f][3] = by;
            }
        }

        const uint32_t* ar0 = At + (mrow + gr) * kFS + tg * 2;
        const uint32_t* ar1 = At + (mrow + gr + 8) * kFS + tg * 2;
        uint2 alo0 = *reinterpret_cast<const uint2*>(ar0);
        uint2 alo1 = *reinterpret_cast<const uint2*>(ar1);
        uint2 ahi0 = *reinterpret_cast<const uint2*>(ar0 + 8);
        uint2 ahi1 = *reinterpret_cast<const uint2*>(ar1 + 8);
        const uint32_t* bp = B_sm + gr * kFS + tg * 2;

#pragma unroll
        for (int f = 0; f < 16; ++f) {
            uint2 blo = *reinterpret_cast<const uint2*>(bp + f * 8 * kFS);
            uint2 bhi = *reinterpret_cast<const uint2*>(bp + f * 8 * kFS + 8);
            mma_bf16(c[f], alo0.x, alo1.x, alo0.y, alo1.y, blo.x, blo.y);
            mma_bf16(c[f], ahi0.x, ahi1.x, ahi0.y, ahi1.y, bhi.x, bhi.y);
        }

        if (!WRITE) {
            float s0 = 0.f, s1 = 0.f;
#pragma unroll
            for (int f = 0; f < 16; ++f) {
                s0 += ex2f(c[f][0]) + ex2f(c[f][1]);
                s1 += ex2f(c[f][2]) + ex2f(c[f][3]);
            }
            s0 += __shfl_xor_sync(0xffffffffu, s0, 1);
            s0 += __shfl_xor_sync(0xffffffffu, s0, 2);
            s1 += __shfl_xor_sync(0xffffffffu, s1, 1);
            s1 += __shfl_xor_sync(0xffffffffu, s1, 2);
            if (tg == 0) {
                g_part[(size_t)blockIdx.x * kRows + row0 + mrow + gr]     = s0;
                g_part[(size_t)blockIdx.x * kRows + row0 + mrow + gr + 8] = s1;
            }
        } else {
            // STG.128: frag pair (2q,2q+1) slots = logical cols 16q+4tg..+3
            float* orow0 = out + (size_t)(row0 + mrow + gr) * kV + n0 + tg * 4;
            float* orow1 = orow0 + (size_t)8 * kV;
#pragma unroll
            for (int q = 0; q < 8; ++q) {
                __stcs(reinterpret_cast<float4*>(orow0 + q * 16),
                       make_float4(c[2 * q][0], c[2 * q][1],
                                   c[2 * q + 1][0], c[2 * q + 1][1]));
                __stcs(reinterpret_cast<float4*>(orow1 + q * 16),
                       make_float4(c[2 * q][2], c[2 * q][3],
                                   c[2 * q + 1][2], c[2 * q + 1][3]));
            }
        }
    }
}

// ---------------------------------------------------------------------------
// Kernel 3: logZ reduce. 256 blocks x 128 threads = 16 rows x 8 t-slices.
// ---------------------------------------------------------------------------
__global__ void logz_kernel() {
    __shared__ float red[8][16];
    int rl    = threadIdx.x & 15;
    int slice = threadIdx.x >> 4;
    int row   = blockIdx.x * 16 + rl;

    float s = 0.f;
#pragma unroll 4
    for (int t = slice; t < kNTiles; t += 8)
        s += g_part[(size_t)t * kRows + row];
    red[slice][rl] = s;
    __syncthreads();

    if (threadIdx.x < 16) {
        float tot = 0.f;
#pragma unroll
        for (int i = 0; i < 8; ++i) tot += red[i][rl];
        g_lz[row] = __logf(tot);
    }
}

// ---------------------------------------------------------------------------
extern "C" void kernel_launch(void* const* d_in, const int* in_sizes, int n_in,
                              void* d_out, int out_size) {
    const int*   tokens = (const int*)d_in[0];
    const float* emb    = (const float*)d_in[1];
    const float* W_ih   = (const float*)d_in[2];
    const float* W_hh   = (const float*)d_in[3];
    const float* b_ih   = (const float*)d_in[4];
    const float* b_hh   = (const float*)d_in[5];
    const float* W_out  = (const float*)d_in[6];
    const float* b_out  = (const float*)d_in[7];
    const float* init_h = (const float*)d_in[8];
    const float* init_c = (const float*)d_in[9];
    float* out = (float*)d_out;

    static cudaStream_t s1 = nullptr;
    static cudaEvent_t evFork = nullptr, evB = nullptr;
    static bool attr_set = false;
    if (!attr_set) {
        cudaFuncSetAttribute(mma_pass<false>,
                             cudaFuncAttributeMaxDynamicSharedMemorySize,
                             kSmemBytes);
        cudaFuncSetAttribute(mma_pass<true>,
                             cudaFuncAttributeMaxDynamicSharedMemorySize,
                             kSmemBytes);
        cudaStreamCreateWithFlags(&s1, cudaStreamNonBlocking);
        cudaEventCreateWithFlags(&evFork, cudaEventDisableTiming);
        cudaEventCreateWithFlags(&evB, cudaEventDisableTiming);
        attr_set = true;
    }

    dim3 grid(kNTiles, kYBlk);

    // fork: prepb (depends only on W_out) overlaps gx+lstm+prepa
    cudaEventRecord(evFork, 0);
    cudaStreamWaitEvent(s1, evFork, 0);
    prepb_kernel<<<kV * 8 / 256, 256, 0, s1>>>(W_out);
    cudaEventRecord(evB, s1);

    gx_kernel<<<kRows / 16, 256>>>(tokens, emb, W_ih, b_ih, b_hh);
    lstm_kernel<<<32, 64>>>(W_hh, init_h, init_c);
    prepa_kernel<<<kRows * 8 / 256, 256>>>();
    cudaStreamWaitEvent(0, evB, 0);

    mma_pass<false><<<grid, 256, kSmemBytes>>>(b_out, out);
    logz_kernel<<<kRows / 16, 128>>>();
    mma_pass<true><<<grid, 256, kSmemBytes>>>(b_out, out);
}

// round 17
// speedup vs baseline: 1.0631x; 1.0184x over previous
#include <cuda_runtime.h>
#include <cuda_bf16.h>
#include <cstdint>

// Problem constants
static constexpr int kS    = 256;
static constexpr int kB    = 16;
static constexpr int kV    = 32000;
static constexpr int kEMB  = 32;
static constexpr int kHID  = 16;
static constexpr int kG    = 4 * kHID;     // 64 gates
static constexpr int kRows = kS * kB;      // 4096
static constexpr int kMT   = 128;          // rows per m tile
static constexpr int kNT   = 128;          // cols per CTA (n tile)
static constexpr int kNTiles = kV / kNT;   // 250
static constexpr int kMTiles = kRows / kMT; // 32
static constexpr int kMLoop = 4;           // m tiles per CTA
static constexpr int kYBlk  = kMTiles / kMLoop;  // 8
static constexpr int kFS   = 24;           // u32 row stride (conflict-free LDS)
static constexpr int kTileU32 = kMT * kFS; // 3072 u32 = 12KB per tile

static constexpr float kLOG2E = 1.4426950408889634f;

// dynamic smem: A[4] tiles + B tile + bias + lz
static constexpr int kSmemBytes =
    (4 * kTileU32 + kTileU32) * 4 + kNT * 4 + kMLoop * kMT * 4;  // 64 KB

// Scratch (static __device__ — no allocations allowed)
__device__ float    g_gx[kS * kB * kG];
__device__ uint32_t g_abf1[kRows * kFS];          // A bf16-frag, x log2(e)
__device__ uint32_t g_abf2[kRows * kFS];          // A bf16-frag, plain
__device__ uint32_t g_bbf[kV * kFS];              // W_out bf16-frag, col-permuted
__device__ float    g_part[kNTiles * kRows];      // per-(ntile,row) exp-sums
__device__ float    g_lz[kRows];                  // per-row logZ

__device__ __forceinline__ float sigf(float x) {
    return 1.0f / (1.0f + __expf(-x));
}
__device__ __forceinline__ float tanhfast(float x) {
    return 2.0f / (1.0f + __expf(-2.0f * x)) - 1.0f;
}
__device__ __forceinline__ float ex2f(float x) {
    float y;
    asm("ex2.approx.ftz.f32 %0, %1;" : "=f"(y) : "f"(x));
    return y;
}
__device__ __forceinline__ uint32_t pack_bf16(float lo, float hi) {
    __nv_bfloat162 h = __floats2bfloat162_rn(lo, hi);
    return *reinterpret_cast<uint32_t*>(&h);
}
__device__ __forceinline__ void mma_bf16(float c[4], uint32_t a0, uint32_t a1,
                                         uint32_t a2, uint32_t a3,
                                         uint32_t b0, uint32_t b1) {
    asm("mma.sync.aligned.m16n8k16.row.col.f32.bf16.bf16.f32 "
        "{%0,%1,%2,%3}, {%4,%5,%6,%7}, {%8,%9}, {%0,%1,%2,%3};"
        : "+f"(c[0]), "+f"(c[1]), "+f"(c[2]), "+f"(c[3])
        : "r"(a0), "r"(a1), "r"(a2), "r"(a3), "r"(b0), "r"(b1));
}
__device__ __forceinline__ void cp16(uint32_t sdst, const void* gsrc) {
    asm volatile("cp.async.cg.shared.global [%0], [%1], 16;"
                 :: "r"(sdst), "l"(gsrc));
}
#define CP_COMMIT() asm volatile("cp.async.commit_group;")
#define CP_WAIT(N)  asm volatile("cp.async.wait_group %0;" :: "n"(N))

// fragment column for k-pair p (p = k/2, 0..15)
__device__ __forceinline__ int fragcol(int p) {
    return 2 * (p & 3) + ((p >> 2) & 1) + (p >> 3) * 8;
}
// Column permutation within a 128-col tile (pass-2 STG.128 enabling):
//   l = 16q + 4tg + e  ->  frag = 2q + (e>>1), pos_in_frag = tg*2 + (e&1)
__device__ __forceinline__ int permrow(int l) {
    int q = l >> 4, tgp = (l >> 2) & 3, e = l & 3;
    return (2 * q + (e >> 1)) * 8 + tgp * 2 + (e & 1);
}

// ---------------------------------------------------------------------------
// Kernel 0: Gx = x@W_ih.T + b_ih + b_hh (R13-proven 1024-block version)
// ---------------------------------------------------------------------------
__global__ void gx_kernel(const int* __restrict__ tokens,
                          const float* __restrict__ emb,
                          const float* __restrict__ W_ih,
                          const float* __restrict__ b_ih,
                          const float* __restrict__ b_hh) {
    __shared__ float ws[kG * 33];
    __shared__ float xs[4][32];
    __shared__ float bb[kG];

    int tid = threadIdx.x;
    for (int i = tid; i < kG * kEMB; i += 256)
        ws[(i >> 5) * 33 + (i & 31)] = W_ih[i];
    if (tid < kG) bb[tid] = b_ih[tid] + b_hh[tid];

    int sb0 = blockIdx.x * 4;
    if (tid < 128) {
        int g = tid >> 5, k = tid & 31;
        xs[g][k] = emb[(size_t)tokens[sb0 + g] * kEMB + k];
    }
    __syncthreads();

    int g = tid >> 6;
    int j = tid & (kG - 1);
    const float* wr = ws + j * 33;
    float a0 = bb[j], a1 = 0.f, a2 = 0.f, a3 = 0.f;
#pragma unroll
    for (int k = 0; k < kEMB; k += 4) {
        a0 += xs[g][k + 0] * wr[k + 0];
        a1 += xs[g][k + 1] * wr[k + 1];
        a2 += xs[g][k + 2] * wr[k + 2];
        a3 += xs[g][k + 3] * wr[k + 3];
    }
    g_gx[(sb0 + g) * kG + j] = (a0 + a1) + (a2 + a3);
}

// ---------------------------------------------------------------------------
// Kernel 1: LSTM recurrence + FUSED bf16 fragment emission (replaces prepa).
// 32 blocks = (2 dirs) x (16 batch lanes), 64 threads, 2 barriers/step.
// Even lanes < 16 pack (h[j], h[j+1]) into bf16x2 and store directly into
// g_abf1/g_abf2 at fragment column fragcol(dir*8 + j/2) — dir0 covers
// k-pairs 0-7, dir1 covers 8-15 (disjoint per row). Off the recurrence path.
// ---------------------------------------------------------------------------
__global__ void lstm_kernel(const float* __restrict__ W_hh,
                            const float* __restrict__ init_h,
                            const float* __restrict__ init_c) {
    int dir = blockIdx.x >> 4;
    int b   = blockIdx.x & 15;
    int j   = threadIdx.x;

    __shared__ float h_sh[kHID];
    __shared__ float gact[kG];

    float w[kHID];
#pragma unroll
    for (int k = 0; k < kHID; ++k) w[k] = W_hh[j * kHID + k];

    float c_reg = 0.f, h_reg = 0.f;
    if (j < kHID) {
        h_reg = init_h[j];
        c_reg = init_c[j];
        h_sh[j] = h_reg;
    }
    __syncthreads();

    int p  = dir ? (kS - 1) : 0;
    int dp = dir ? -1 : 1;
    float gx_next = g_gx[(p * kB + b) * kG + j];
    int colbase = dir * 8;

    for (int step = 0; step < kS; ++step, p += dp) {
        float gxv = gx_next;
        if (step < kS - 1) gx_next = g_gx[((p + dp) * kB + b) * kG + j];

        // emit hidden (pre-consume) directly as bf16 fragment pairs
        if (j < kHID && (j & 1) == 0) {
            float h0v = h_sh[j], h1v = h_sh[j + 1];
            int col = fragcol(colbase + (j >> 1));
            int r = p * kB + b;
            g_abf2[r * kFS + col] = pack_bf16(h0v, h1v);
            g_abf1[r * kFS + col] = pack_bf16(h0v * kLOG2E, h1v * kLOG2E);
        }

        float a0 = 0.f, a1 = 0.f, a2 = 0.f, a3 = 0.f;
#pragma unroll
        for (int k = 0; k < kHID; k += 4) {
            a0 += w[k + 0] * h_sh[k + 0];
            a1 += w[k + 1] * h_sh[k + 1];
            a2 += w[k + 2] * h_sh[k + 2];
            a3 += w[k + 3] * h_sh[k + 3];
        }
        float pre = gxv + ((a0 + a1) + (a2 + a3));
        gact[j] = (j >= 32 && j < 48) ? tanhfast(pre) : sigf(pre);
        __syncthreads();

        if (j < kHID) {
            float ig = gact[j];
            float fg = gact[kHID + j];
            float gg = gact[2 * kHID + j];
            float og = gact[3 * kHID + j];
            c_reg = fg * c_reg + ig * gg;
            h_reg = og * tanhfast(c_reg);
            h_sh[j] = h_reg;
        }
        __syncthreads();
    }
}

// ---------------------------------------------------------------------------
// Prep kernel: W_out -> bf16 fragment order with within-tile col permutation.
// ---------------------------------------------------------------------------
__global__ void prepb_kernel(const float* __restrict__ W_out) {
    int i = blockIdx.x * 256 + threadIdx.x;       // over kV*8 float4s
    float4 v = reinterpret_cast<const float4*>(W_out)[i];
    int n = i >> 3, j = i & 7;
    int rp = (n & ~127) + permrow(n & 127);       // permuted physical row
    uint32_t* dst = g_bbf + (size_t)rp * kFS;
    dst[fragcol(2 * j)]     = pack_bf16(v.x, v.y);
    dst[fragcol(2 * j + 1)] = pack_bf16(v.z, v.w);
}

// ---------------------------------------------------------------------------
// Kernel 2: bf16 tensor-core logits GEMM. Grid (250, 8). cp.async prefetch of
// B + 4 A tiles at CTA start; m-loop is wait/barrier/MMA only.
// Pass 1 (WRITE=false): occ 3, Σ f32-ex2 -> g_part.
// Pass 2 (WRITE=true):  occ 2, acc init = b - logZ -> STG.128 direct stores.
// ---------------------------------------------------------------------------
template <bool WRITE>
__global__ void __launch_bounds__(256, WRITE ? 2 : 3)
mma_pass(const float* __restrict__ b_out, float* __restrict__ out) {
    extern __shared__ uint32_t dynsm[];
    uint32_t* A_sm   = dynsm;                       // [4][3072]
    uint32_t* B_sm   = dynsm + 4 * kTileU32;        // [3072]
    float*    bias_sm = reinterpret_cast<float*>(dynsm + 5 * kTileU32);  // [128]
    float*    lz_sm   = bias_sm + kNT;              // [512]

    int tid  = threadIdx.x;
    int warp = tid >> 5;
    int lane = tid & 31;
    int tg   = lane & 3;
    int gr   = lane >> 2;
    int n0   = blockIdx.x * kNT;
    int mrow = warp * 16;
    int rbase = blockIdx.y * kMLoop * kMT;          // 512 rows per CTA

    // B tile: contiguous 12KB from g_bbf
    {
        uint32_t bdst = (uint32_t)__cvta_generic_to_shared(B_sm);
        const uint4* src = reinterpret_cast<const uint4*>(
            g_bbf + (size_t)n0 * kFS);
        for (int i = tid; i < kTileU32 / 4; i += 256)
            cp16(bdst + i * 16, src + i);
        CP_COMMIT();
    }
    // A tiles: 4 contiguous 12KB blocks
    const uint32_t* asrc_base = WRITE ? g_abf2 : g_abf1;
#pragma unroll
    for (int mi = 0; mi < kMLoop; ++mi) {
        uint32_t adst = (uint32_t)__cvta_generic_to_shared(A_sm + mi * kTileU32);
        const uint4* src = reinterpret_cast<const uint4*>(
            asrc_base + (size_t)(rbase + mi * kMT) * kFS);
        for (int i = tid; i < kTileU32 / 4; i += 256)
            cp16(adst + i * 16, src + i);
        CP_COMMIT();
    }
    // bias (PHYSICAL fragment order, matching permuted B) + lz
    if (tid < kNT) {
        int frag = tid >> 3, pos = tid & 7;
        int l = 16 * (frag >> 1) + 4 * (pos >> 1) + 2 * (frag & 1) + (pos & 1);
        float bv = b_out[n0 + l];
        bias_sm[tid] = WRITE ? bv : bv * kLOG2E;
    }
    if (WRITE) {
        for (int i = tid; i < kMLoop * kMT; i += 256)
            lz_sm[i] = g_lz[rbase + i];
    }

#pragma unroll
    for (int mi = 0; mi < kMLoop; ++mi) {
        switch (mi) {   // wait until B + A[0..mi] groups complete
            case 0:  CP_WAIT(3); break;
            case 1:  CP_WAIT(2); break;
            case 2:  CP_WAIT(1); break;
            default: CP_WAIT(0); break;
        }
        __syncthreads();

        int row0 = rbase + mi * kMT;
        const uint32_t* At = A_sm + mi * kTileU32;

        float c[16][4];
#pragma unroll
        for (int f = 0; f < 16; ++f) {
            float bx = bias_sm[f * 8 + tg * 2];
            float by = bias_sm[f * 8 + tg * 2 + 1];
            if (WRITE) {
                float z0 = lz_sm[mi * kMT + mrow + gr];
                float z1 = lz_sm[mi * kMT + mrow + gr + 8];
                c[f][0] = bx - z0; c[f][1] = by - z0;
                c[f][2] = bx - z1; c[f][3] = by - z1;
            } else {
                c[f][0] = bx; c[f][1] = by;
                c[f][2] = bx; c[f][3] = by;
            }
        }

        const uint32_t* ar0 = At + (mrow + gr) * kFS + tg * 2;
        const uint32_t* ar1 = At + (mrow + gr + 8) * kFS + tg * 2;
        uint2 alo0 = *reinterpret_cast<const uint2*>(ar0);
        uint2 alo1 = *reinterpret_cast<const uint2*>(ar1);
        uint2 ahi0 = *reinterpret_cast<const uint2*>(ar0 + 8);
        uint2 ahi1 = *reinterpret_cast<const uint2*>(ar1 + 8);
        const uint32_t* bp = B_sm + gr * kFS + tg * 2;

#pragma unroll
        for (int f = 0; f < 16; ++f) {
            uint2 blo = *reinterpret_cast<const uint2*>(bp + f * 8 * kFS);
            uint2 bhi = *reinterpret_cast<const uint2*>(bp + f * 8 * kFS + 8);
            mma_bf16(c[f], alo0.x, alo1.x, alo0.y, alo1.y, blo.x, blo.y);
            mma_bf16(c[f], ahi0.x, ahi1.x, ahi0.y, ahi1.y, bhi.x, bhi.y);
        }

        if (!WRITE) {
            float s0 = 0.f, s1 = 0.f;
#pragma unroll
            for (int f = 0; f < 16; ++f) {
                s0 += ex2f(c[f][0]) + ex2f(c[f][1]);
                s1 += ex2f(c[f][2]) + ex2f(c[f][3]);
            }
            s0 += __shfl_xor_sync(0xffffffffu, s0, 1);
            s0 += __shfl_xor_sync(0xffffffffu, s0, 2);
            s1 += __shfl_xor_sync(0xffffffffu, s1, 1);
            s1 += __shfl_xor_sync(0xffffffffu, s1, 2);
            if (tg == 0) {
                g_part[(size_t)blockIdx.x * kRows + row0 + mrow + gr]     = s0;
                g_part[(size_t)blockIdx.x * kRows + row0 + mrow + gr + 8] = s1;
            }
        } else {
            // STG.128: frag pair (2q,2q+1) slots = logical cols 16q+4tg..+3
            float* orow0 = out + (size_t)(row0 + mrow + gr) * kV + n0 + tg * 4;
            float* orow1 = orow0 + (size_t)8 * kV;
#pragma unroll
            for (int q = 0; q < 8; ++q) {
                __stcs(reinterpret_cast<float4*>(orow0 + q * 16),
                       make_float4(c[2 * q][0], c[2 * q][1],
                                   c[2 * q + 1][0], c[2 * q + 1][1]));
                __stcs(reinterpret_cast<float4*>(orow1 + q * 16),
                       make_float4(c[2 * q][2], c[2 * q][3],
                                   c[2 * q + 1][2], c[2 * q + 1][3]));
            }
        }
    }
}

// ---------------------------------------------------------------------------
// Kernel 3: logZ reduce. 256 blocks x 128 threads = 16 rows x 8 t-slices.
// ---------------------------------------------------------------------------
__global__ void logz_kernel() {
    __shared__ float red[8][16];
    int rl    = threadIdx.x & 15;
    int slice = threadIdx.x >> 4;
    int row   = blockIdx.x * 16 + rl;

    float s = 0.f;
#pragma unroll 4
    for (int t = slice; t < kNTiles; t += 8)
        s += g_part[(size_t)t * kRows + row];
    red[slice][rl] = s;
    __syncthreads();

    if (threadIdx.x < 16) {
        float tot = 0.f;
#pragma unroll
        for (int i = 0; i < 8; ++i) tot += red[i][rl];
        g_lz[row] = __logf(tot);
    }
}

// ---------------------------------------------------------------------------
extern "C" void kernel_launch(void* const* d_in, const int* in_sizes, int n_in,
                              void* d_out, int out_size) {
    const int*   tokens = (const int*)d_in[0];
    const float* emb    = (const float*)d_in[1];
    const float* W_ih   = (const float*)d_in[2];
    const float* W_hh   = (const float*)d_in[3];
    const float* b_ih   = (const float*)d_in[4];
    const float* b_hh   = (const float*)d_in[5];
    const float* W_out  = (const float*)d_in[6];
    const float* b_out  = (const float*)d_in[7];
    const float* init_h = (const float*)d_in[8];
    const float* init_c = (const float*)d_in[9];
    float* out = (float*)d_out;

    static cudaStream_t s1 = nullptr;
    static cudaEvent_t evFork = nullptr, evB = nullptr;
    static bool attr_set = false;
    if (!attr_set) {
        cudaFuncSetAttribute(mma_pass<false>,
                             cudaFuncAttributeMaxDynamicSharedMemorySize,
                             kSmemBytes);
        cudaFuncSetAttribute(mma_pass<true>,
                             cudaFuncAttributeMaxDynamicSharedMemorySize,
                             kSmemBytes);
        cudaStreamCreateWithFlags(&s1, cudaStreamNonBlocking);
        cudaEventCreateWithFlags(&evFork, cudaEventDisableTiming);
        cudaEventCreateWithFlags(&evB, cudaEventDisableTiming);
        attr_set = true;
    }

    dim3 grid(kNTiles, kYBlk);

    // fork: prepb (depends only on W_out) overlaps gx+lstm
    cudaEventRecord(evFork, 0);
    cudaStreamWaitEvent(s1, evFork, 0);
    prepb_kernel<<<kV * 8 / 256, 256, 0, s1>>>(W_out);
    cudaEventRecord(evB, s1);

    gx_kernel<<<(kS * kB) / 4, 256>>>(tokens, emb, W_ih, b_ih, b_hh);
    lstm_kernel<<<32, 64>>>(W_hh, init_h, init_c);
    cudaStreamWaitEvent(0, evB, 0);

    mma_pass<false><<<grid, 256, kSmemBytes>>>(b_out, out);
    logz_kernel<<<kRows / 16, 128>>>();
    mma_pass<true><<<grid, 256, kSmemBytes>>>(b_out, out);
}